// round 8
// baseline (speedup 1.0000x reference)
#include <cuda_runtime.h>
#include <stdint.h>

// Problem constants
#define B 8
#define H 12
#define L 1024
#define D 768
#define KSEL 512
#define HL (H * L)                  // 12288 rows per batch
#define L4 (L / 4)                  // 256 float4 per score row
#define D4 (D / 4)                  // 192 float4 per token row
#define NBLK 768                    // single co-resident wave (6/SM x 148 = 888)
#define BPB 192                     // blocks per batch (per phase)
#define ROWS_PB 64                  // rows per block per phase
#define NROWS_OUT (B * (KSEL + 1))  // 4104 output token rows

// Scratch (device globals). Zero at load; kernel restores zeros every call
// -> graph-replay safe.
__device__ float g_imp[B * L];
__device__ int   g_selidx[B * KSEL];
__device__ int   g_count[B];
__device__ int   g_flag[B];
__device__ int   g_done;

// ---------------------------------------------------------------------------
// Colsum phase: 64 rows of batch b starting at row0, float4 streaming,
// constant trip count (unroll 16), atomic flush into g_imp.
// ---------------------------------------------------------------------------
__device__ __forceinline__ void colsum_phase(
    const float4* __restrict__ scores4, float* __restrict__ imp,
    int b, int row0, int t)
{
    const float4* base = scores4 + ((size_t)b * HL + row0) * L4 + t;
    float4 acc = make_float4(0.f, 0.f, 0.f, 0.f);
#pragma unroll 16
    for (int r = 0; r < ROWS_PB; ++r) {
        const float4 x = __ldcs(base + (size_t)r * L4);
        acc.x += x.x; acc.y += x.y; acc.z += x.z; acc.w += x.w;
    }
    float* dst = imp + b * L + 4 * t;
    atomicAdd(dst + 0, acc.x);
    atomicAdd(dst + 1, acc.y);
    atomicAdd(dst + 2, acc.z);
    atomicAdd(dst + 3, acc.w);
}

// ---------------------------------------------------------------------------
// Select phase (runs on the last-arriving block of batch b): radix top-K
// select + compact + mask write + scratch reset + flag release.
// ---------------------------------------------------------------------------
__device__ __forceinline__ void select_phase(
    const float* __restrict__ amask, float* __restrict__ imp,
    int* __restrict__ selidx, int* __restrict__ count, int* __restrict__ flag,
    float* __restrict__ out, int b, int t, int lane, int wid)
{
    __threadfence();   // acquire: all batch-b atomics visible

    const float4 iv = *((const float4*)(imp + b * L) + t);

    unsigned k[4];
    {
        const float f[4] = {iv.x, iv.y, iv.z, iv.w};
#pragma unroll
        for (int i = 0; i < 4; ++i) {
            const unsigned ub = __float_as_uint(f[i]);
            k[i] = ub ^ ((ub & 0x80000000u) ? 0xFFFFFFFFu : 0x80000000u);
        }
    }

    __shared__ int      hist[256];
    __shared__ unsigned s_pref;
    __shared__ int      s_k;
    __shared__ int      wtot[8];

    if (t == 0) { s_pref = 0u; s_k = KSEL; }
    __syncthreads();

    // 4-pass byte radix select: 512th-largest key + tie quota
#pragma unroll
    for (int pass = 0; pass < 4; ++pass) {
        const int shift = 24 - 8 * pass;
        const unsigned pref = s_pref;
        const int kcur = s_k;

        hist[t] = 0;
        __syncthreads();
#pragma unroll
        for (int i = 0; i < 4; ++i) {
            const bool active = (pass == 0) ||
                (((k[i] ^ pref) >> (shift + 8)) == 0u);
            if (active) atomicAdd(&hist[(k[i] >> shift) & 0xFF], 1);
        }
        __syncthreads();

        const int h = hist[t];
        int v = h;
#pragma unroll
        for (int d = 1; d < 32; d <<= 1) {
            const int n = __shfl_down_sync(0xffffffffu, v, d);
            if (lane + d < 32) v += n;
        }
        const int wsum = __shfl_sync(0xffffffffu, v, 0);
        if (lane == 0) wtot[wid] = wsum;
        __syncthreads();
        int above = 0;
#pragma unroll
        for (int w = 0; w < 8; ++w) if (w > wid) above += wtot[w];
        const int ge = v + above;
        const int gt = ge - h;
        if (gt < kcur && ge >= kcur) {   // exactly one bin fires
            s_pref = pref | ((unsigned)t << shift);
            s_k    = kcur - gt;
        }
        __syncthreads();
    }

    const unsigned T  = s_pref;
    const int      kq = s_k;     // tie slots, lowest indices win

    // tie ranking (ascending index)
    bool tie[4];
    int tiecnt = 0;
#pragma unroll
    for (int i = 0; i < 4; ++i) { tie[i] = (k[i] == T); tiecnt += tie[i]; }
    int incl = tiecnt;
#pragma unroll
    for (int d = 1; d < 32; d <<= 1) {
        const int n = __shfl_up_sync(0xffffffffu, incl, d);
        if (lane >= d) incl += n;
    }
    if (lane == 31) wtot[wid] = incl;
    __syncthreads();
    int base = 0;
#pragma unroll
    for (int w = 0; w < 8; ++w) if (w < wid) base += wtot[w];
    int trank = base + incl - tiecnt;

    bool sel[4];
    int selcnt = 0;
#pragma unroll
    for (int i = 0; i < 4; ++i) {
        bool sl = (k[i] > T);
        if (tie[i]) { sl = (trank < kq); ++trank; }
        sel[i] = sl; selcnt += sl;
    }
    __syncthreads();

    // compaction scan (ascending index)
    int sincl = selcnt;
#pragma unroll
    for (int d = 1; d < 32; d <<= 1) {
        const int n = __shfl_up_sync(0xffffffffu, sincl, d);
        if (lane >= d) sincl += n;
    }
    if (lane == 31) wtot[wid] = sincl;
    __syncthreads();
    int sbase = 0;
#pragma unroll
    for (int w = 0; w < 8; ++w) if (w < wid) sbase += wtot[w];
    int pos = sbase + sincl - selcnt;

#pragma unroll
    for (int i = 0; i < 4; ++i) {
        if (sel[i]) { selidx[b * KSEL + pos] = 4 * t + i; ++pos; }
    }
    __syncthreads();

    // final attention mask (513 floats)
    float* mout = out + (size_t)B * (KSEL + 1) * D + (size_t)b * (KSEL + 1);
    for (int r = t; r <= KSEL; r += 256) {
        if (r == 0) mout[0] = 0.f;
        else        mout[r] = amask[(size_t)b * L + selidx[b * KSEL + r - 1]];
    }

    // reset scratch for next replay
    *((float4*)(imp + b * L) + t) = make_float4(0.f, 0.f, 0.f, 0.f);
    if (t == 0) count[b] = 0;

    // release: selidx ready for this batch
    __threadfence();
    __syncthreads();
    if (t == 0) atomicExch(&flag[b], 1);
}

// ---------------------------------------------------------------------------
// Gather pass: copy up to 3 output token rows (flattened indices f0,f0+NBLK,
// f0+2*NBLK). t==0 spins on each row's batch flag, loads j into smem; then
// 192 lanes issue 3 independent float4 loads and 3 stores.
// ---------------------------------------------------------------------------
__device__ __forceinline__ void gather_pass(
    const float* __restrict__ hidden, const int* __restrict__ selidx,
    volatile int* __restrict__ flag, float* __restrict__ out,
    int f0, int t)
{
    __shared__ int s_j[3];
    __shared__ int s_b[3];
    __shared__ int s_r[3];

    if (t == 0) {
#pragma unroll
        for (int q = 0; q < 3; ++q) {
            const int f = f0 + q * NBLK;
            if (f < NROWS_OUT) {
                const int b = f / (KSEL + 1);
                const int r = f % (KSEL + 1);
                while (flag[b] == 0) __nanosleep(64);
                __threadfence();   // acquire selidx
                s_b[q] = b;
                s_r[q] = r;
                s_j[q] = (r == 0) ? 0 : selidx[b * KSEL + r - 1];
            } else {
                s_b[q] = -1;
            }
        }
    }
    __syncthreads();

    if (t < D4) {
        float4 v[3];
#pragma unroll
        for (int q = 0; q < 3; ++q) {
            if (s_b[q] >= 0) {
                const float4* src = (const float4*)(hidden
                    + ((size_t)s_b[q] * L + s_j[q]) * D) + t;
                v[q] = *src;
            }
        }
#pragma unroll
        for (int q = 0; q < 3; ++q) {
            if (s_b[q] >= 0) {
                float4* dst = (float4*)(out
                    + ((size_t)s_b[q] * (KSEL + 1) + s_r[q]) * D) + t;
                *dst = v[q];
            }
        }
    }
    __syncthreads();
}

// ---------------------------------------------------------------------------
// Fused kernel. Block i: q = i & 3, blk = i >> 2.
//   phase 1: colsum batch q      rows [blk*64, blk*64+64)   -> maybe select
//   phase 2: colsum batch 4+q    rows [blk*64, blk*64+64)   -> maybe select
//   phase 3: gather rows f = i, i+768, ..., A-batches first by construction
//            (flags for batches 0..3 were set ~30us earlier).
// ---------------------------------------------------------------------------
__global__ void __launch_bounds__(256, 6) router_fused_kernel(
    const float4* __restrict__ scores4, const float* __restrict__ amask,
    const float* __restrict__ hidden,
    float* __restrict__ imp, int* __restrict__ selidx,
    int* __restrict__ count, int* __restrict__ flag, int* __restrict__ done,
    float* __restrict__ out)
{
    const int i = blockIdx.x;
    const int t = threadIdx.x;
    const int lane = t & 31;
    const int wid  = t >> 5;
    const int q   = i & 3;
    const int blk = i >> 2;          // 0..191
    const int row0 = blk * ROWS_PB;

    __shared__ int s_trigger;

    // ---- phase 1: group-A batch ----
    {
        const int b = q;
        colsum_phase(scores4, imp, b, row0, t);
        __threadfence();
        __syncthreads();
        if (t == 0) s_trigger = (atomicAdd(&count[b], 1) == BPB - 1);
        __syncthreads();
        if (s_trigger)
            select_phase(amask, imp, selidx, count, flag, out, b, t, lane, wid);
    }

    // ---- phase 2: group-B batch ----
    {
        const int b = 4 + q;
        colsum_phase(scores4, imp, b, row0, t);
        __threadfence();
        __syncthreads();
        if (t == 0) s_trigger = (atomicAdd(&count[b], 1) == BPB - 1);
        __syncthreads();
        if (s_trigger)
            select_phase(amask, imp, selidx, count, flag, out, b, t, lane, wid);
    }

    // ---- phase 3: gather (rows i, i+768, ..., < 4104; two passes of 3) ----
    gather_pass(hidden, selidx, (volatile int*)flag, out, i, t);
    gather_pass(hidden, selidx, (volatile int*)flag, out, i + 3 * NBLK, t);

    // ---- completion: last block resets flags for next replay ----
    __syncthreads();
    if (t == 0) {
        if (atomicAdd(done, 1) == NBLK - 1) {
#pragma unroll
            for (int b = 0; b < B; ++b) flag[b] = 0;
            *done = 0;
        }
    }
}

// ---------------------------------------------------------------------------
extern "C" void kernel_launch(void* const* d_in, const int* in_sizes, int n_in,
                              void* d_out, int out_size)
{
    const float* hidden = (const float*)d_in[0];   // [B, L, D]
    const float* amask  = (const float*)d_in[1];   // [B, 1, 1, L]
    const float* scores = (const float*)d_in[2];   // [B, H, L, L]
    float* out = (float*)d_out;                    // tokens then mask, f32

    float* d_imp;
    int *d_selidx, *d_count, *d_flag, *d_done;
    cudaGetSymbolAddress((void**)&d_imp,    g_imp);
    cudaGetSymbolAddress((void**)&d_selidx, g_selidx);
    cudaGetSymbolAddress((void**)&d_count,  g_count);
    cudaGetSymbolAddress((void**)&d_flag,   g_flag);
    cudaGetSymbolAddress((void**)&d_done,   g_done);

    router_fused_kernel<<<NBLK, 256>>>(
        (const float4*)scores, amask, hidden,
        d_imp, d_selidx, d_count, d_flag, d_done, out);
}

// round 9
// speedup vs baseline: 1.1288x; 1.1288x over previous
#include <cuda_runtime.h>
#include <stdint.h>

// Problem constants
#define B 8
#define H 12
#define L 1024
#define D 768
#define KSEL 512
#define HL (H * L)                       // 12288 rows per batch
#define SPLITS 128
#define ROWS_PER_SPLIT (HL / SPLITS)     // 96
#define L4 (L / 4)                       // 256 float4 per score row
#define D4 (D / 4)                       // 192 float4 per token row

// Scratch (device globals). Zero at load; kernel restores zeros every call
// -> graph-replay safe.
__device__ float g_imp[B * L];
__device__ int   g_selidx[B * KSEL];
__device__ int   g_count[B];

// ---------------------------------------------------------------------------
// Kernel 1: column sums (128-way split, float4 streaming, f32 atomics into
// g_imp); per-batch last-arriving block runs the radix top-K select +
// compact + mask write. Blocks trigger the programmatic launch of the
// gather kernel right after their flush, so gather's dispatch overlaps the
// select tail.
// grid (B, SPLITS), block 256.
// ---------------------------------------------------------------------------
__global__ void __launch_bounds__(256) colsum_select_kernel(
    const float4* __restrict__ scores4, const float* __restrict__ amask,
    float* __restrict__ imp, int* __restrict__ selidx,
    int* __restrict__ count, float* __restrict__ out)
{
    const int b = blockIdx.x;
    const int s = blockIdx.y;
    const int t = threadIdx.x;
    const int lane = t & 31;
    const int wid  = t >> 5;

    // ---- colsum phase: stream 96 rows, accumulate 1 float4 per thread ----
    {
        const float4* base =
            scores4 + ((size_t)b * HL + (size_t)s * ROWS_PER_SPLIT) * L4 + t;
        float4 acc = make_float4(0.f, 0.f, 0.f, 0.f);
#pragma unroll 16
        for (int r = 0; r < ROWS_PER_SPLIT; ++r) {
            const float4 x = __ldcs(base + (size_t)r * L4);
            acc.x += x.x; acc.y += x.y; acc.z += x.z; acc.w += x.w;
        }
        float* dst = imp + b * L + 4 * t;
        atomicAdd(dst + 0, acc.x);
        atomicAdd(dst + 1, acc.y);
        atomicAdd(dst + 2, acc.z);
        atomicAdd(dst + 3, acc.w);
    }

    // ---- let the dependent gather kernel start dispatching ----
#if __CUDA_ARCH__ >= 900
    if (t == 0) cudaTriggerProgrammaticLaunchCompletion();
#endif

    // ---- arrival: last block per batch runs the selection ----
    __threadfence();
    __syncthreads();
    __shared__ int s_ticket;
    if (t == 0) s_ticket = atomicAdd(&count[b], 1);
    __syncthreads();
    if (s_ticket != SPLITS - 1) return;
    __threadfence();               // acquire: all batch-b atomics visible

    // ---- read importance: thread t owns columns 4t..4t+3 ----
    const float4 iv = *((const float4*)(imp + b * L) + t);

    unsigned k[4];
    {
        const float f[4] = {iv.x, iv.y, iv.z, iv.w};
#pragma unroll
        for (int i = 0; i < 4; ++i) {
            const unsigned ub = __float_as_uint(f[i]);
            k[i] = ub ^ ((ub & 0x80000000u) ? 0xFFFFFFFFu : 0x80000000u);
        }
    }

    __shared__ int      hist[256];
    __shared__ unsigned s_pref;
    __shared__ int      s_k;
    __shared__ int      wtot[8];

    if (t == 0) { s_pref = 0u; s_k = KSEL; }
    __syncthreads();

    // ---- 4-pass byte radix select: 512th-largest key + tie quota ----
#pragma unroll
    for (int pass = 0; pass < 4; ++pass) {
        const int shift = 24 - 8 * pass;
        const unsigned pref = s_pref;
        const int kcur = s_k;

        hist[t] = 0;
        __syncthreads();
#pragma unroll
        for (int i = 0; i < 4; ++i) {
            const bool active = (pass == 0) ||
                (((k[i] ^ pref) >> (shift + 8)) == 0u);
            if (active) atomicAdd(&hist[(k[i] >> shift) & 0xFF], 1);
        }
        __syncthreads();

        const int h = hist[t];
        int v = h;
#pragma unroll
        for (int d = 1; d < 32; d <<= 1) {
            const int n = __shfl_down_sync(0xffffffffu, v, d);
            if (lane + d < 32) v += n;
        }
        const int wsum = __shfl_sync(0xffffffffu, v, 0);
        if (lane == 0) wtot[wid] = wsum;
        __syncthreads();
        int above = 0;
#pragma unroll
        for (int w = 0; w < 8; ++w) if (w > wid) above += wtot[w];
        const int ge = v + above;        // active keys with bin >= t
        const int gt = ge - h;
        if (gt < kcur && ge >= kcur) {   // exactly one bin fires
            s_pref = pref | ((unsigned)t << shift);
            s_k    = kcur - gt;
        }
        __syncthreads();
    }

    const unsigned T  = s_pref;   // threshold key (512th-largest)
    const int      kq = s_k;      // tie slots (>= 1), lowest indices win

    // ---- tie ranking (ascending index) via block scan ----
    bool tie[4];
    int tiecnt = 0;
#pragma unroll
    for (int i = 0; i < 4; ++i) { tie[i] = (k[i] == T); tiecnt += tie[i]; }

    int incl = tiecnt;
#pragma unroll
    for (int d = 1; d < 32; d <<= 1) {
        const int n = __shfl_up_sync(0xffffffffu, incl, d);
        if (lane >= d) incl += n;
    }
    if (lane == 31) wtot[wid] = incl;
    __syncthreads();
    int base = 0;
#pragma unroll
    for (int w = 0; w < 8; ++w) if (w < wid) base += wtot[w];
    int trank = base + incl - tiecnt;    // exclusive prefix of ties

    bool sel[4];
    int selcnt = 0;
#pragma unroll
    for (int i = 0; i < 4; ++i) {
        bool sl = (k[i] > T);
        if (tie[i]) { sl = (trank < kq); ++trank; }
        sel[i] = sl; selcnt += sl;
    }
    __syncthreads();                     // wtot reuse

    // ---- compaction scan (ascending index) ----
    int sincl = selcnt;
#pragma unroll
    for (int d = 1; d < 32; d <<= 1) {
        const int n = __shfl_up_sync(0xffffffffu, sincl, d);
        if (lane >= d) sincl += n;
    }
    if (lane == 31) wtot[wid] = sincl;
    __syncthreads();
    int sbase = 0;
#pragma unroll
    for (int w = 0; w < 8; ++w) if (w < wid) sbase += wtot[w];
    int pos = sbase + sincl - selcnt;    // exclusive prefix

#pragma unroll
    for (int i = 0; i < 4; ++i) {
        if (sel[i]) { selidx[b * KSEL + pos] = 4 * t + i; ++pos; }
    }

    __syncthreads();   // selidx writes visible block-wide

    // ---- final attention mask for this batch (513 floats) ----
    float* mout = out + (size_t)B * (KSEL + 1) * D + (size_t)b * (KSEL + 1);
    for (int r = t; r <= KSEL; r += 256) {
        if (r == 0) mout[0] = 0.f;
        else        mout[r] = amask[(size_t)b * L + selidx[b * KSEL + r - 1]];
    }

    // ---- reset scratch for the next replay ----
    *((float4*)(imp + b * L) + t) = make_float4(0.f, 0.f, 0.f, 0.f);
    if (t == 0) count[b] = 0;
}

// ---------------------------------------------------------------------------
// Kernel 2 (programmatic dependent launch): gather token rows.
// grid (33, B), block 512: one warp per output row (16 rows/block),
// 6 independent float4 loads per lane. Row 0 = class token (j=0).
// ---------------------------------------------------------------------------
__global__ void __launch_bounds__(512) gather_kernel(
    const float* __restrict__ hs, const int* __restrict__ selidx,
    float* __restrict__ out)
{
#if __CUDA_ARCH__ >= 900
    cudaGridDependencySynchronize();
#endif
    const int w    = threadIdx.x >> 5;       // 0..15 row slot
    const int lane = threadIdx.x & 31;
    const int r = blockIdx.x * 16 + w;       // 0..527
    const int b = blockIdx.y;
    if (r > KSEL) return;

    const int j = (r == 0) ? 0 : selidx[b * KSEL + r - 1];

    const float4* src = (const float4*)(hs + ((size_t)b * L + j) * D) + lane;
    float4* dst = (float4*)(out + ((size_t)b * (KSEL + 1) + r) * D) + lane;

    float4 v[6];
#pragma unroll
    for (int q = 0; q < 6; ++q) v[q] = src[32 * q];
#pragma unroll
    for (int q = 0; q < 6; ++q) dst[32 * q] = v[q];
}

// ---------------------------------------------------------------------------
extern "C" void kernel_launch(void* const* d_in, const int* in_sizes, int n_in,
                              void* d_out, int out_size)
{
    const float* hidden = (const float*)d_in[0];   // [B, L, D]
    const float* amask  = (const float*)d_in[1];   // [B, 1, 1, L]
    const float* scores = (const float*)d_in[2];   // [B, H, L, L]
    float* out = (float*)d_out;                    // tokens then mask, f32

    float* d_imp;
    int *d_selidx, *d_count;
    cudaGetSymbolAddress((void**)&d_imp,    g_imp);
    cudaGetSymbolAddress((void**)&d_selidx, g_selidx);
    cudaGetSymbolAddress((void**)&d_count,  g_count);

    dim3 gridA(B, SPLITS);
    colsum_select_kernel<<<gridA, 256>>>(
        (const float4*)scores, amask, d_imp, d_selidx, d_count, out);

    // Gather launched as a programmatic dependent launch: dispatch overlaps
    // the primary kernel's select tail; cudaGridDependencySynchronize()
    // inside the kernel guarantees selidx visibility.
    cudaLaunchAttribute attrs[1];
    attrs[0].id = cudaLaunchAttributeProgrammaticStreamSerialization;
    attrs[0].val.programmaticStreamSerializationAllowed = 1;

    cudaLaunchConfig_t cfg = {};
    cfg.gridDim  = dim3(33, B);
    cfg.blockDim = dim3(512);
    cfg.dynamicSmemBytes = 0;
    cfg.stream = 0;
    cfg.attrs = attrs;
    cfg.numAttrs = 1;
    cudaLaunchKernelEx(&cfg, gather_kernel, hidden,
                       (const int*)d_selidx, out);
}

// round 10
// speedup vs baseline: 1.1350x; 1.0055x over previous
#include <cuda_runtime.h>
#include <stdint.h>

// Problem constants
#define B 8
#define H 12
#define L 1024
#define D 768
#define KSEL 512
#define HL (H * L)                       // 12288 rows per batch
#define SPLITS 96
#define ROWS_PER_SPLIT (HL / SPLITS)     // 128
#define L4 (L / 4)                       // 256 float4 per score row
#define D4 (D / 4)                       // 192 float4 per token row

// Scratch (device globals). Zero at load; kernel restores zeros every call
// -> graph-replay safe.
__device__ float g_imp[B * L];
__device__ int   g_selidx[B * KSEL];
__device__ int   g_count[B];
__device__ int   g_flag[B];
__device__ int   g_done[B];

// ---------------------------------------------------------------------------
// Single fused kernel, grid (B, SPLITS), block 256.
//   1) colsum: stream 128 rows (float4, unroll 16), f32 atomics into g_imp
//   2) last-arriving block per batch: radix top-K select + compact + mask,
//      reset scratch, release flag[b]
//   3) all blocks of batch b: spin on flag[b] (released by an already-running
//      block of the same batch -> no co-residency requirement), then gather
//      rows r = s, s+96, ... with 6 independent float4 loads in flight.
// ---------------------------------------------------------------------------
__global__ void __launch_bounds__(256) router_fused_kernel(
    const float4* __restrict__ scores4, const float* __restrict__ amask,
    const float* __restrict__ hidden,
    float* __restrict__ imp, int* __restrict__ selidx,
    int* __restrict__ count, int* __restrict__ flag, int* __restrict__ done,
    float* __restrict__ out)
{
    const int b = blockIdx.x;
    const int s = blockIdx.y;
    const int t = threadIdx.x;
    const int lane = t & 31;
    const int wid  = t >> 5;

    // ---- 1) colsum phase ----
    {
        const float4* base =
            scores4 + ((size_t)b * HL + (size_t)s * ROWS_PER_SPLIT) * L4 + t;
        float4 acc = make_float4(0.f, 0.f, 0.f, 0.f);
#pragma unroll 16
        for (int r = 0; r < ROWS_PER_SPLIT; ++r) {
            const float4 x = __ldcs(base + (size_t)r * L4);
            acc.x += x.x; acc.y += x.y; acc.z += x.z; acc.w += x.w;
        }
        float* dst = imp + b * L + 4 * t;
        atomicAdd(dst + 0, acc.x);
        atomicAdd(dst + 1, acc.y);
        atomicAdd(dst + 2, acc.z);
        atomicAdd(dst + 3, acc.w);
    }

    // ---- arrival ----
    __threadfence();
    __syncthreads();
    __shared__ int s_ticket;
    if (t == 0) s_ticket = atomicAdd(&count[b], 1);
    __syncthreads();

    // ---- 2) select on the last-arriving block ----
    if (s_ticket == SPLITS - 1) {
        __threadfence();               // acquire: all batch-b atomics visible

        const float4 iv = *((const float4*)(imp + b * L) + t);

        unsigned k[4];
        {
            const float f[4] = {iv.x, iv.y, iv.z, iv.w};
#pragma unroll
            for (int i = 0; i < 4; ++i) {
                const unsigned ub = __float_as_uint(f[i]);
                k[i] = ub ^ ((ub & 0x80000000u) ? 0xFFFFFFFFu : 0x80000000u);
            }
        }

        __shared__ int      hist[256];
        __shared__ unsigned s_pref;
        __shared__ int      s_k;
        __shared__ int      wtot[8];

        if (t == 0) { s_pref = 0u; s_k = KSEL; }
        __syncthreads();

        // 4-pass byte radix select: 512th-largest key + tie quota
#pragma unroll
        for (int pass = 0; pass < 4; ++pass) {
            const int shift = 24 - 8 * pass;
            const unsigned pref = s_pref;
            const int kcur = s_k;

            hist[t] = 0;
            __syncthreads();
#pragma unroll
            for (int i = 0; i < 4; ++i) {
                const bool active = (pass == 0) ||
                    (((k[i] ^ pref) >> (shift + 8)) == 0u);
                if (active) atomicAdd(&hist[(k[i] >> shift) & 0xFF], 1);
            }
            __syncthreads();

            const int h = hist[t];
            int v = h;
#pragma unroll
            for (int d = 1; d < 32; d <<= 1) {
                const int n = __shfl_down_sync(0xffffffffu, v, d);
                if (lane + d < 32) v += n;
            }
            const int wsum = __shfl_sync(0xffffffffu, v, 0);
            if (lane == 0) wtot[wid] = wsum;
            __syncthreads();
            int above = 0;
#pragma unroll
            for (int w = 0; w < 8; ++w) if (w > wid) above += wtot[w];
            const int ge = v + above;        // active keys with bin >= t
            const int gt = ge - h;
            if (gt < kcur && ge >= kcur) {   // exactly one bin fires
                s_pref = pref | ((unsigned)t << shift);
                s_k    = kcur - gt;
            }
            __syncthreads();
        }

        const unsigned T  = s_pref;
        const int      kq = s_k;      // tie slots (>= 1), lowest indices win

        // tie ranking (ascending index) via block scan
        bool tie[4];
        int tiecnt = 0;
#pragma unroll
        for (int i = 0; i < 4; ++i) { tie[i] = (k[i] == T); tiecnt += tie[i]; }

        int incl = tiecnt;
#pragma unroll
        for (int d = 1; d < 32; d <<= 1) {
            const int n = __shfl_up_sync(0xffffffffu, incl, d);
            if (lane >= d) incl += n;
        }
        if (lane == 31) wtot[wid] = incl;
        __syncthreads();
        int base = 0;
#pragma unroll
        for (int w = 0; w < 8; ++w) if (w < wid) base += wtot[w];
        int trank = base + incl - tiecnt;

        bool sel[4];
        int selcnt = 0;
#pragma unroll
        for (int i = 0; i < 4; ++i) {
            bool sl = (k[i] > T);
            if (tie[i]) { sl = (trank < kq); ++trank; }
            sel[i] = sl; selcnt += sl;
        }
        __syncthreads();

        // compaction scan (ascending index)
        int sincl = selcnt;
#pragma unroll
        for (int d = 1; d < 32; d <<= 1) {
            const int n = __shfl_up_sync(0xffffffffu, sincl, d);
            if (lane >= d) sincl += n;
        }
        if (lane == 31) wtot[wid] = sincl;
        __syncthreads();
        int sbase = 0;
#pragma unroll
        for (int w = 0; w < 8; ++w) if (w < wid) sbase += wtot[w];
        int pos = sbase + sincl - selcnt;

#pragma unroll
        for (int i = 0; i < 4; ++i) {
            if (sel[i]) { selidx[b * KSEL + pos] = 4 * t + i; ++pos; }
        }
        __syncthreads();

        // final attention mask (513 floats)
        float* mout = out + (size_t)B * (KSEL + 1) * D
                          + (size_t)b * (KSEL + 1);
        for (int r = t; r <= KSEL; r += 256) {
            if (r == 0) mout[0] = 0.f;
            else        mout[r] = amask[(size_t)b * L
                                        + selidx[b * KSEL + r - 1]];
        }

        // reset scratch for next replay
        *((float4*)(imp + b * L) + t) = make_float4(0.f, 0.f, 0.f, 0.f);
        if (t == 0) count[b] = 0;

        // release: selidx ready for this batch
        __threadfence();
        __syncthreads();
        if (t == 0) atomicExch(&flag[b], 1);
    }

    // ---- 3) gather phase ----
    // wait for own batch's selidx (releaser is an already-running block)
    if (t == 0) {
        while (((volatile int*)flag)[b] == 0) __nanosleep(32);
    }
    __syncthreads();
    __threadfence();   // acquire

    // preload indices for rows r = s + 96*q (q = 0..5; r <= 512)
    __shared__ int s_j[6];
    if (t < 6) {
        const int r = s + SPLITS * t;
        if (r <= KSEL)
            s_j[t] = (r == 0) ? 0 : selidx[b * KSEL + r - 1];
    }
    __syncthreads();

    if (t < D4) {
        float4 v[6];
#pragma unroll
        for (int q = 0; q < 6; ++q) {
            const int r = s + SPLITS * q;
            if (r <= KSEL) {
                const float4* src = (const float4*)(hidden
                    + ((size_t)b * L + s_j[q]) * D) + t;
                v[q] = *src;
            }
        }
#pragma unroll
        for (int q = 0; q < 6; ++q) {
            const int r = s + SPLITS * q;
            if (r <= KSEL) {
                float4* dst = (float4*)(out
                    + ((size_t)b * (KSEL + 1) + r) * D) + t;
                *dst = v[q];
            }
        }
    }

    // ---- completion: last gatherer of each batch resets flags ----
    __syncthreads();
    if (t == 0) {
        if (atomicAdd(&done[b], 1) == SPLITS - 1) {
            done[b] = 0;
            flag[b] = 0;
        }
    }
}

// ---------------------------------------------------------------------------
extern "C" void kernel_launch(void* const* d_in, const int* in_sizes, int n_in,
                              void* d_out, int out_size)
{
    const float* hidden = (const float*)d_in[0];   // [B, L, D]
    const float* amask  = (const float*)d_in[1];   // [B, 1, 1, L]
    const float* scores = (const float*)d_in[2];   // [B, H, L, L]
    float* out = (float*)d_out;                    // tokens then mask, f32

    float* d_imp;
    int *d_selidx, *d_count, *d_flag, *d_done;
    cudaGetSymbolAddress((void**)&d_imp,    g_imp);
    cudaGetSymbolAddress((void**)&d_selidx, g_selidx);
    cudaGetSymbolAddress((void**)&d_count,  g_count);
    cudaGetSymbolAddress((void**)&d_flag,   g_flag);
    cudaGetSymbolAddress((void**)&d_done,   g_done);

    dim3 grid(B, SPLITS);
    router_fused_kernel<<<grid, 256>>>(
        (const float4*)scores, amask, hidden,
        d_imp, d_selidx, d_count, d_flag, d_done, out);
}